// round 16
// baseline (speedup 1.0000x reference)
#include <cuda_runtime.h>
#include <cuda_fp16.h>
#include <cstdint>

// ============================================================================
// ExtractorMLP, R14: persistent CTAs + W2 in SMEM + warp-specialized pipeline,
// fixed for latency: 512 thr = 8 compute warps (2 per SMSP, m16n32 tiles)
// + 8 gather warps, double-buffered 32-edge H subtiles.
//   P = emb@W1_top + b1, Q = emb@W1_bot  (fp16, L2-resident, prep kernels)
//   per edge: out = W3 . relu( relu(P[col]+Q[row]) @ W2 + b2 ) + b3
// ============================================================================

#define NTHREADS 512
#define HID      128
#define SUB      32        // edges per subtile
#define NBLK     148
#define MAXN     10240

// ---- main-kernel smem layout (bytes) ----
#define W2S_OFF  0                       // 131072 (8192 uint4)
#define H_OFF    131072                  // 2 x 32768 (H bufs, rows 1KB swizzled)
#define SCR_OFF  (H_OFF + 65536)         // 2 x 2048 (readout scratch)
#define FLAG_OFF (SCR_OFF + 4096)
#define SMEM_TOTAL (FLAG_OFF + 16)       // 200784 B -> 1 CTA/SM

// W1 fragments: uint4 g_w1[nc(4)][ks(16: 0-7=P,8-15=Q)][wn(4)][fp(2)][lane(32)]
// W2 fragments: uint4 g_w2[ks(32)][wn(4)][fp(2)][lane(32)]
__device__ __align__(128) uint4 g_w1[4 * 16 * 4 * 2 * 32];   // 256KB
__device__ __align__(128) uint4 g_w2[32 * 4 * 2 * 32];       // 128KB
__device__ __align__(128) __half g_P[MAXN * 512];            // 10.5MB
__device__ __align__(128) __half g_Q[MAXN * 512];            // 10.5MB

// ---------------------------------------------------------------- helpers ---
__device__ __forceinline__ uint32_t smem_u32(const void* p) {
    uint32_t a;
    asm("{ .reg .u64 t; cvta.to.shared.u64 t, %1; cvt.u32.u64 %0, t; }"
        : "=r"(a) : "l"(p));
    return a;
}
__device__ __forceinline__ void ldsm4(uint32_t* r, uint32_t a) {
    asm volatile("ldmatrix.sync.aligned.m8n8.x4.shared.b16 {%0,%1,%2,%3}, [%4];"
                 : "=r"(r[0]), "=r"(r[1]), "=r"(r[2]), "=r"(r[3]) : "r"(a));
}
__device__ __forceinline__ void mma16816(float* c, const uint32_t* a,
                                         uint32_t b0, uint32_t b1) {
    asm("mma.sync.aligned.m16n8k16.row.col.f32.f16.f16.f32 "
        "{%0,%1,%2,%3}, {%4,%5,%6,%7}, {%8,%9}, {%0,%1,%2,%3};"
        : "+f"(c[0]), "+f"(c[1]), "+f"(c[2]), "+f"(c[3])
        : "r"(a[0]), "r"(a[1]), "r"(a[2]), "r"(a[3]), "r"(b0), "r"(b1));
}
__device__ __forceinline__ uint32_t pkh2(float v0, float v1) {
    uint32_t r;
    asm("{ .reg .f16 a, b; cvt.rn.f16.f32 a, %1; cvt.rn.f16.f32 b, %2;\n\t"
        "mov.b32 %0, {a, b}; }" : "=r"(r) : "f"(v0), "f"(v1));
    return r;
}
// relu(p + q) on packed fp16x2 (b1 pre-folded into P)
__device__ __forceinline__ uint32_t h2fuse(uint32_t p, uint32_t q) {
    __half2 r = __hmax2(__hadd2(*(__half2*)&p, *(__half2*)&q),
                        __float2half2_rn(0.f));
    return *(uint32_t*)&r;
}
__device__ __forceinline__ uint4 h4fuse(uint4 p, uint4 q) {
    uint4 r;
    r.x = h2fuse(p.x, q.x);
    r.y = h2fuse(p.y, q.y);
    r.z = h2fuse(p.z, q.z);
    r.w = h2fuse(p.w, q.w);
    return r;
}

#define LOADB2(dst, p) do {                 \
    dst[0] = __ldg((p));                    \
    dst[1] = __ldg((p) + 32);               \
} while (0)

// m32 x n32 kstep (used by prep_pq): 8 MMAs from 2 ldsm + 2 B uint4.
__device__ __forceinline__ void kstep8(float (&acc)[2][4][4],
                                       uint32_t aB0, uint32_t aB1,
                                       uint32_t offA, const uint4 (&q)[2]) {
    uint32_t a0[4], a1[4];
    ldsm4(a0, aB0 + offA);
    ldsm4(a1, aB1 + offA);
#pragma unroll
    for (int fp = 0; fp < 2; ++fp) {
        mma16816(acc[0][fp * 2],     a0, q[fp].x, q[fp].y);
        mma16816(acc[1][fp * 2],     a1, q[fp].x, q[fp].y);
        mma16816(acc[0][fp * 2 + 1], a0, q[fp].z, q[fp].w);
        mma16816(acc[1][fp * 2 + 1], a1, q[fp].z, q[fp].w);
    }
}

// ------------------------------------------------------ prep 1: pack W ------
__global__ void prep_pack(const float* __restrict__ W1,
                          const float* __restrict__ W2) {
    int gid = blockIdx.x * blockDim.x + threadIdx.x;
    if (gid < 256 * 512) {
        int k = gid >> 9, n = gid & 511;                   // W1 (k, n)
        __half hv = __float2half_rn(W1[k * 512 + n]);
        int half_ = k >> 7, kl = k & 127;
        int ks = half_ * 8 + (kl >> 4), kin = kl & 15;
        int nc = n >> 7, ninc = n & 127;
        int wn = ninc >> 5, nin = ninc & 31;
        int frag = nin >> 3, fp = frag >> 1, which = frag & 1;
        int lane = (nin & 7) * 4 + ((kin >> 1) & 3);
        int breg = (kin >> 3) & 1, hlf = kin & 1;
        size_t idx = ((((size_t)nc * 16 + ks) * 4 + wn) * 2 + fp) * 32 + lane;
        ((unsigned short*)g_w1)[idx * 8 + which * 4 + breg * 2 + hlf] =
            __half_as_ushort(hv);
    } else if (gid < 256 * 512 + 512 * 128) {
        int g2 = gid - 256 * 512;                          // W2 (k, n)
        int k = g2 >> 7, n = g2 & 127;
        __half hv = __float2half_rn(W2[k * 128 + n]);
        int ks = k >> 4, kin = k & 15;
        int wn = n >> 5, nin = n & 31;
        int frag = nin >> 3, fp = frag >> 1, which = frag & 1;
        int lane = (nin & 7) * 4 + ((kin >> 1) & 3);
        int breg = (kin >> 3) & 1, hlf = kin & 1;
        size_t idx = (((size_t)ks * 4 + wn) * 2 + fp) * 32 + lane;
        ((unsigned short*)g_w2)[idx * 8 + which * 4 + breg * 2 + hlf] =
            __half_as_ushort(hv);
    }
}

// --------------------------------------------- prep 2: P,Q = emb @ W1 halves
__global__ void __launch_bounds__(128, 4)
prep_pq(const float* __restrict__ emb, const float* __restrict__ b1,
        int n_nodes) {
    __shared__ __align__(1024) char smA[32 * 256];   // [32 m][128 k] fp16 sw
    const uint32_t sa = smem_u32(smA);
    const int t = threadIdx.x;
    const int lane = t & 31, wn = t >> 5;
    const int lc = lane >> 4, x7 = lane & 7;
    const int nb = blockIdx.x * 32;

    {
        int m = t >> 2, qd = t & 3;
        int node = min(nb + m, n_nodes - 1);
        const float4* src = (const float4*)(emb + (size_t)node * HID);
        int xm = m & 7;
#pragma unroll
        for (int j = 0; j < 4; ++j) {
            int cch = qd * 4 + j;
            float4 v0 = __ldg(&src[cch * 2]);
            float4 v1 = __ldg(&src[cch * 2 + 1]);
            uint4 o;
            o.x = pkh2(v0.x, v0.y); o.y = pkh2(v0.z, v0.w);
            o.z = pkh2(v1.x, v1.y); o.w = pkh2(v1.z, v1.w);
            *(uint4*)(smA + m * 256 + ((cch ^ xm) * 16)) = o;
        }
    }
    __syncthreads();

    const int rA = lane & 15;
    const uint32_t aB0 = sa + rA * 256, aB1 = aB0 + 16 * 256;

#pragma unroll 1
    for (int nc = 0; nc < 4; ++nc) {
#pragma unroll 1
        for (int hf = 0; hf < 2; ++hf) {
            float acc[2][4][4];
#pragma unroll
            for (int a = 0; a < 2; ++a)
#pragma unroll
                for (int b = 0; b < 4; ++b)
#pragma unroll
                    for (int d = 0; d < 4; ++d) acc[a][b][d] = 0.f;
            const uint4* bq =
                g_w1 + ((((size_t)nc * 16 + hf * 8) * 4 + wn) * 2) * 32 + lane;
            uint4 q[2], qn[2];
            LOADB2(q, bq);
#pragma unroll
            for (int ks = 0; ks < 8; ks += 2) {
                LOADB2(qn, bq + (ks + 1) * 256);
                kstep8(acc, aB0, aB1, (uint32_t)(((ks * 2 + lc) ^ x7) << 4), q);
                if (ks + 2 < 8) LOADB2(q, bq + (ks + 2) * 256);
                kstep8(acc, aB0, aB1, (uint32_t)((((ks + 1) * 2 + lc) ^ x7) << 4), qn);
            }
            __half* dst = hf ? g_Q : g_P;
#pragma unroll
            for (int tm = 0; tm < 2; ++tm)
#pragma unroll
                for (int tn = 0; tn < 4; ++tn) {
                    int r0 = nb + tm * 16 + (lane >> 2);
                    int n0 = nc * 128 + wn * 32 + tn * 8 + (lane & 3) * 2;
                    float f0 = acc[tm][tn][0], f1 = acc[tm][tn][1];
                    float f2 = acc[tm][tn][2], f3 = acc[tm][tn][3];
                    if (hf == 0) {   // fold b1 into P (fp32 add, then pack)
                        float bb0 = __ldg(b1 + n0), bb1 = __ldg(b1 + n0 + 1);
                        f0 += bb0; f1 += bb1; f2 += bb0; f3 += bb1;
                    }
                    if (r0 < n_nodes)
                        *(uint32_t*)(dst + (size_t)r0 * 512 + n0) = pkh2(f0, f1);
                    if (r0 + 8 < n_nodes)
                        *(uint32_t*)(dst + (size_t)(r0 + 8) * 512 + n0) = pkh2(f2, f3);
                }
        }
    }
}

// ------------------------------------------------------------ main kernel ---
// gather one 32-edge subtile into buf (warps 8-15; 4 edges per warp)
__device__ __forceinline__ void gather_subtile(
    char* smem, int bufsel, long long s, const void* ei_raw, int is64,
    int E, int n_nodes, int warp, int lane) {
    char* buf = smem + H_OFF + bufsel * 32768;
    const int g = warp - 8;
    const long long eb = s * SUB;
    const int* ei32 = (const int*)ei_raw;
    const long long* ei64 = (const long long*)ei_raw;
#pragma unroll
    for (int j = 0; j < 4; ++j) {
        int m = g * 4 + j;
        long long ee = eb + m; if (ee >= E) ee = E - 1;
        int colid = is64 ? (int)ei64[ee] : ei32[ee];
        int rowid = is64 ? (int)ei64[E + ee] : ei32[E + ee];
        colid = min(max(colid, 0), n_nodes - 1);
        rowid = min(max(rowid, 0), n_nodes - 1);
        const uint4* pP = (const uint4*)(g_P + (size_t)colid * 512);
        const uint4* pQ = (const uint4*)(g_Q + (size_t)rowid * 512);
        uint4 p0 = __ldg(pP + lane),      q0 = __ldg(pQ + lane);
        uint4 p1 = __ldg(pP + 32 + lane), q1 = __ldg(pQ + 32 + lane);
        int xm = m & 7;
        *(uint4*)(buf + m * 1024 + ((lane ^ xm) * 16)) = h4fuse(p0, q0);
        *(uint4*)(buf + m * 1024 + (((lane + 32) ^ xm) * 16)) = h4fuse(p1, q1);
    }
}

__global__ void __launch_bounds__(NTHREADS, 1)
mlp_hmma_kernel(const void* __restrict__ ei_raw,
                const float* __restrict__ b2, const float* __restrict__ W3,
                const float* __restrict__ b3,
                float* __restrict__ out, int E, int n_nodes) {
    extern __shared__ __align__(1024) char smem[];
    const uint32_t sb = smem_u32(smem);
    const int t = threadIdx.x;
    const int lane = t & 31, warp = t >> 5;
    const int lc = lane >> 4, x7 = lane & 7;
    const int nsub = (E + SUB - 1) / SUB;

    // ---- W2 fragments -> smem (once per CTA) ----
    {
        uint4* w2s = (uint4*)(smem + W2S_OFF);
#pragma unroll
        for (int i = 0; i < 16; ++i)
            w2s[t + i * NTHREADS] = __ldg(g_w2 + t + i * NTHREADS);
    }
    // ---- edge_index dtype probe ----
    if (t == 0) *(int*)(smem + FLAG_OFF) = 1;
    __syncthreads();
    const int* ei32p = (const int*)ei_raw;
    if (t < 128 && ei32p[2 * t + 1] != 0)
        *(int*)(smem + FLAG_OFF) = 0;                      // benign race
    __syncthreads();
    const int is64 = *(int*)(smem + FLAG_OFF);

    // ---- prologue: gather first subtile into buf 0 ----
    if (warp >= 8 && blockIdx.x < nsub)
        gather_subtile(smem, 0, blockIdx.x, ei_raw, is64, E, n_nodes, warp, lane);

    // compute-warp constants: warp = wnn*2 + wm  (warps 0..7)
    const int wm = warp & 1, wnn = warp >> 1;
    const uint4* bq2 = (const uint4*)(smem + W2S_OFF) + (wnn * 2) * 32 + lane;
    const int rowA = wm * 16 + (lane & 15);
    // hoisted epilogue constants (per tn: b2/W3 pairs)
    float bb0[4], bb1[4], w30[4], w31[4];
    if (warp < 8) {
#pragma unroll
        for (int tn = 0; tn < 4; ++tn) {
            int n0 = wnn * 32 + tn * 8 + (lane & 3) * 2;
            bb0[tn] = __ldg(b2 + n0);  bb1[tn] = __ldg(b2 + n0 + 1);
            w30[tn] = __ldg(W3 + n0);  w31[tn] = __ldg(W3 + n0 + 1);
        }
    }
    const float b3v = __ldg(b3);
    __syncthreads();

#pragma unroll 1
    for (int li = 0;; ++li) {
        long long s = blockIdx.x + (long long)li * NBLK;
        if (s >= nsub) break;
        const int cur = li & 1;

        if (warp < 8) {
            // ---- GEMM2: m16 x n32 this warp, K=512 from H[cur] ----
            const uint32_t aB = sb + H_OFF + cur * 32768 + rowA * 1024;
            float acc[4][4];
#pragma unroll
            for (int b = 0; b < 4; ++b)
#pragma unroll
                for (int d = 0; d < 4; ++d) acc[b][d] = 0.f;
#pragma unroll 8
            for (int ks = 0; ks < 32; ++ks) {
                uint4 q0 = bq2[ks * 256];
                uint4 q1 = bq2[ks * 256 + 32];
                uint32_t a[4];
                ldsm4(a, aB + (uint32_t)(((ks * 2 + lc) ^ x7) << 4));
                mma16816(acc[0], a, q0.x, q0.y);
                mma16816(acc[1], a, q0.z, q0.w);
                mma16816(acc[2], a, q1.x, q1.y);
                mma16816(acc[3], a, q1.z, q1.w);
            }
            // partial readout -> scratch[cur]
            float pr0 = 0.f, pr1 = 0.f;
#pragma unroll
            for (int tn = 0; tn < 4; ++tn) {
                pr0 += fmaxf(acc[tn][0] + bb0[tn], 0.f) * w30[tn];
                pr0 += fmaxf(acc[tn][1] + bb1[tn], 0.f) * w31[tn];
                pr1 += fmaxf(acc[tn][2] + bb0[tn], 0.f) * w30[tn];
                pr1 += fmaxf(acc[tn][3] + bb1[tn], 0.f) * w31[tn];
            }
            float* scr = (float*)(smem + SCR_OFF + cur * 2048);  // [32][16]
            int row = wm * 16 + (lane >> 2);
            scr[row * 16 + wnn * 4 + (lane & 3)] = pr0;
            scr[(row + 8) * 16 + wnn * 4 + (lane & 3)] = pr1;
        } else {
            // ---- gather next subtile into buf 1-cur ----
            long long snext = s + NBLK;
            if (snext < nsub)
                gather_subtile(smem, 1 - cur, snext, ei_raw, is64, E,
                               n_nodes, warp, lane);
        }
        __syncthreads();

        // ---- final reduce + store (warp 0; scratch[cur] not rewritten until
        // after the next __syncthreads) ----
        if (warp == 0) {
            const float* scr = (const float*)(smem + SCR_OFF + cur * 2048);
            float ssum = 0.f;
#pragma unroll
            for (int i = 0; i < 16; ++i) ssum += scr[lane * 16 + i];
            long long e = s * SUB + lane;
            if (e < E) out[e] = ssum + b3v;
        }
    }
}

// --------------------------------------------------------------- launcher ---
extern "C" void kernel_launch(void* const* d_in, const int* in_sizes, int n_in,
                              void* d_out, int out_size) {
    const float* emb = (const float*)d_in[0];
    const void*  ei  = d_in[1];          // edge_index [2,E], int32 or int64 (probed)
    const float* W1 = (const float*)d_in[3];
    const float* b1 = (const float*)d_in[4];
    const float* W2 = (const float*)d_in[5];
    const float* b2 = (const float*)d_in[6];
    const float* W3 = (const float*)d_in[7];
    const float* b3 = (const float*)d_in[8];
    float* out = (float*)d_out;

    int E = in_sizes[1] / 2;
    int n_nodes = in_sizes[0] / HID;
    if (n_nodes > MAXN) n_nodes = MAXN;   // static-table capacity guard

    prep_pack<<<(256 * 512 + 512 * 128 + 255) / 256, 256>>>(W1, W2);
    prep_pq<<<(n_nodes + 31) / 32, 128>>>(emb, b1, n_nodes);
    cudaFuncSetAttribute(mlp_hmma_kernel,
                         cudaFuncAttributeMaxDynamicSharedMemorySize, SMEM_TOTAL);
    mlp_hmma_kernel<<<NBLK, NTHREADS, SMEM_TOTAL>>>(ei, b2, W3, b3,
                                                    out, E, n_nodes);
}

// round 17
// speedup vs baseline: 1.3075x; 1.3075x over previous
#include <cuda_runtime.h>
#include <cuda_fp16.h>
#include <cstdint>

// ============================================================================
// ExtractorMLP, R15: R12 structure with M_CTA=96 (12 warps, 2 CTAs/SM =
// same 24 warps/SM as R12) to amortize W2 L2 traffic 1.31 GB -> 853 MB.
//   P = emb@W1_top + b1, Q = emb@W1_bot  (fp16, L2-resident, prep kernels)
//   H[e] = relu(P[col]+Q[row]);  out = W3 . relu(H@W2 + b2) + b3
// Main kernel: warp-per-row coalesced gather -> smem H -> mma.sync fp16 GEMM2.
// ============================================================================

#define NTHREADS 384
#define HID      128
#define M_CTA    96
#define MAXN     10240     // max nodes supported by static P/Q tables

// ---- main-kernel smem layout (bytes) ----
#define IDX_OFF  0            // 192 node indices (int)
#define FLAG_OFF 784
#define H_OFF    1024         // [96 m][512 k] fp16, swizzled rows 1KB (96KB)
#define SMEM_TOTAL (H_OFF + 98304)   // 99328 B -> 2 CTAs/SM

// W1 fragments: uint4 g_w1[nc(4)][ks(16: 0-7=P,8-15=Q)][wn(4)][fp(2)][lane(32)]
// W2 fragments: uint4 g_w2[ks(32)][wn(4)][fp(2)][lane(32)]
__device__ __align__(128) uint4 g_w1[4 * 16 * 4 * 2 * 32];   // 256KB
__device__ __align__(128) uint4 g_w2[32 * 4 * 2 * 32];       // 128KB
__device__ __align__(128) __half g_P[MAXN * 512];            // 10.5MB
__device__ __align__(128) __half g_Q[MAXN * 512];            // 10.5MB

// ---------------------------------------------------------------- helpers ---
__device__ __forceinline__ uint32_t smem_u32(const void* p) {
    uint32_t a;
    asm("{ .reg .u64 t; cvta.to.shared.u64 t, %1; cvt.u32.u64 %0, t; }"
        : "=r"(a) : "l"(p));
    return a;
}
__device__ __forceinline__ void ldsm4(uint32_t* r, uint32_t a) {
    asm volatile("ldmatrix.sync.aligned.m8n8.x4.shared.b16 {%0,%1,%2,%3}, [%4];"
                 : "=r"(r[0]), "=r"(r[1]), "=r"(r[2]), "=r"(r[3]) : "r"(a));
}
__device__ __forceinline__ void mma16816(float* c, const uint32_t* a,
                                         uint32_t b0, uint32_t b1) {
    asm("mma.sync.aligned.m16n8k16.row.col.f32.f16.f16.f32 "
        "{%0,%1,%2,%3}, {%4,%5,%6,%7}, {%8,%9}, {%0,%1,%2,%3};"
        : "+f"(c[0]), "+f"(c[1]), "+f"(c[2]), "+f"(c[3])
        : "r"(a[0]), "r"(a[1]), "r"(a[2]), "r"(a[3]), "r"(b0), "r"(b1));
}
__device__ __forceinline__ uint32_t pkh2(float v0, float v1) {
    uint32_t r;
    asm("{ .reg .f16 a, b; cvt.rn.f16.f32 a, %1; cvt.rn.f16.f32 b, %2;\n\t"
        "mov.b32 %0, {a, b}; }" : "=r"(r) : "f"(v0), "f"(v1));
    return r;
}
// relu(p + q) on packed fp16x2 (b1 pre-folded into P)
__device__ __forceinline__ uint32_t h2fuse(uint32_t p, uint32_t q) {
    __half2 r = __hmax2(__hadd2(*(__half2*)&p, *(__half2*)&q),
                        __float2half2_rn(0.f));
    return *(uint32_t*)&r;
}
__device__ __forceinline__ uint4 h4fuse(uint4 p, uint4 q) {
    uint4 r;
    r.x = h2fuse(p.x, q.x);
    r.y = h2fuse(p.y, q.y);
    r.z = h2fuse(p.z, q.z);
    r.w = h2fuse(p.w, q.w);
    return r;
}

#define LOADB2(dst, p) do {                 \
    dst[0] = __ldg((p));                    \
    dst[1] = __ldg((p) + 32);               \
} while (0)

// m32 x n32 kstep: 8 MMAs from 2 ldsm + 2 preloaded uint4.
__device__ __forceinline__ void kstep8(float (&acc)[2][4][4],
                                       uint32_t aB0, uint32_t aB1,
                                       uint32_t offA, const uint4 (&q)[2]) {
    uint32_t a0[4], a1[4];
    ldsm4(a0, aB0 + offA);
    ldsm4(a1, aB1 + offA);
#pragma unroll
    for (int fp = 0; fp < 2; ++fp) {
        mma16816(acc[0][fp * 2],     a0, q[fp].x, q[fp].y);
        mma16816(acc[1][fp * 2],     a1, q[fp].x, q[fp].y);
        mma16816(acc[0][fp * 2 + 1], a0, q[fp].z, q[fp].w);
        mma16816(acc[1][fp * 2 + 1], a1, q[fp].z, q[fp].w);
    }
}

// ------------------------------------------------------ prep 1: pack W ------
__global__ void prep_pack(const float* __restrict__ W1,
                          const float* __restrict__ W2) {
    int gid = blockIdx.x * blockDim.x + threadIdx.x;
    if (gid < 256 * 512) {
        int k = gid >> 9, n = gid & 511;                   // W1 (k, n)
        __half hv = __float2half_rn(W1[k * 512 + n]);
        int half_ = k >> 7, kl = k & 127;
        int ks = half_ * 8 + (kl >> 4), kin = kl & 15;
        int nc = n >> 7, ninc = n & 127;
        int wn = ninc >> 5, nin = ninc & 31;
        int frag = nin >> 3, fp = frag >> 1, which = frag & 1;
        int lane = (nin & 7) * 4 + ((kin >> 1) & 3);
        int breg = (kin >> 3) & 1, hlf = kin & 1;
        size_t idx = ((((size_t)nc * 16 + ks) * 4 + wn) * 2 + fp) * 32 + lane;
        ((unsigned short*)g_w1)[idx * 8 + which * 4 + breg * 2 + hlf] =
            __half_as_ushort(hv);
    } else if (gid < 256 * 512 + 512 * 128) {
        int g2 = gid - 256 * 512;                          // W2 (k, n)
        int k = g2 >> 7, n = g2 & 127;
        __half hv = __float2half_rn(W2[k * 128 + n]);
        int ks = k >> 4, kin = k & 15;
        int wn = n >> 5, nin = n & 31;
        int frag = nin >> 3, fp = frag >> 1, which = frag & 1;
        int lane = (nin & 7) * 4 + ((kin >> 1) & 3);
        int breg = (kin >> 3) & 1, hlf = kin & 1;
        size_t idx = (((size_t)ks * 4 + wn) * 2 + fp) * 32 + lane;
        ((unsigned short*)g_w2)[idx * 8 + which * 4 + breg * 2 + hlf] =
            __half_as_ushort(hv);
    }
}

// --------------------------------------------- prep 2: P,Q = emb @ W1 halves
__global__ void __launch_bounds__(128, 4)
prep_pq(const float* __restrict__ emb, const float* __restrict__ b1,
        int n_nodes) {
    __shared__ __align__(1024) char smA[32 * 256];   // [32 m][128 k] fp16 sw
    const uint32_t sa = smem_u32(smA);
    const int t = threadIdx.x;
    const int lane = t & 31, wn = t >> 5;
    const int lc = lane >> 4, x7 = lane & 7;
    const int nb = blockIdx.x * 32;

    {
        int m = t >> 2, qd = t & 3;
        int node = min(nb + m, n_nodes - 1);
        const float4* src = (const float4*)(emb + (size_t)node * HID);
        int xm = m & 7;
#pragma unroll
        for (int j = 0; j < 4; ++j) {
            int cch = qd * 4 + j;
            float4 v0 = __ldg(&src[cch * 2]);
            float4 v1 = __ldg(&src[cch * 2 + 1]);
            uint4 o;
            o.x = pkh2(v0.x, v0.y); o.y = pkh2(v0.z, v0.w);
            o.z = pkh2(v1.x, v1.y); o.w = pkh2(v1.z, v1.w);
            *(uint4*)(smA + m * 256 + ((cch ^ xm) * 16)) = o;
        }
    }
    __syncthreads();

    const int rA = lane & 15;
    const uint32_t aB0 = sa + rA * 256, aB1 = aB0 + 16 * 256;

#pragma unroll 1
    for (int nc = 0; nc < 4; ++nc) {
#pragma unroll 1
        for (int hf = 0; hf < 2; ++hf) {
            float acc[2][4][4];
#pragma unroll
            for (int a = 0; a < 2; ++a)
#pragma unroll
                for (int b = 0; b < 4; ++b)
#pragma unroll
                    for (int d = 0; d < 4; ++d) acc[a][b][d] = 0.f;
            const uint4* bq =
                g_w1 + ((((size_t)nc * 16 + hf * 8) * 4 + wn) * 2) * 32 + lane;
            uint4 q[2], qn[2];
            LOADB2(q, bq);
#pragma unroll
            for (int ks = 0; ks < 8; ks += 2) {
                LOADB2(qn, bq + (ks + 1) * 256);
                kstep8(acc, aB0, aB1, (uint32_t)(((ks * 2 + lc) ^ x7) << 4), q);
                if (ks + 2 < 8) LOADB2(q, bq + (ks + 2) * 256);
                kstep8(acc, aB0, aB1, (uint32_t)((((ks + 1) * 2 + lc) ^ x7) << 4), qn);
            }
            __half* dst = hf ? g_Q : g_P;
#pragma unroll
            for (int tm = 0; tm < 2; ++tm)
#pragma unroll
                for (int tn = 0; tn < 4; ++tn) {
                    int r0 = nb + tm * 16 + (lane >> 2);
                    int n0 = nc * 128 + wn * 32 + tn * 8 + (lane & 3) * 2;
                    float f0 = acc[tm][tn][0], f1 = acc[tm][tn][1];
                    float f2 = acc[tm][tn][2], f3 = acc[tm][tn][3];
                    if (hf == 0) {   // fold b1 into P (fp32 add, then pack)
                        float bb0 = __ldg(b1 + n0), bb1 = __ldg(b1 + n0 + 1);
                        f0 += bb0; f1 += bb1; f2 += bb0; f3 += bb1;
                    }
                    if (r0 < n_nodes)
                        *(uint32_t*)(dst + (size_t)r0 * 512 + n0) = pkh2(f0, f1);
                    if (r0 + 8 < n_nodes)
                        *(uint32_t*)(dst + (size_t)(r0 + 8) * 512 + n0) = pkh2(f2, f3);
                }
        }
    }
}

// ------------------------------------------------------------ main kernel ---
__global__ void __launch_bounds__(NTHREADS, 2)
mlp_hmma_kernel(const void* __restrict__ ei_raw,
                const float* __restrict__ b2, const float* __restrict__ W3,
                const float* __restrict__ b3,
                float* __restrict__ out, int E, int n_nodes) {
    extern __shared__ __align__(1024) char smem[];
    const uint32_t sb = smem_u32(smem);
    const int t = threadIdx.x;
    const int lane = t & 31, warp = t >> 5;
    const int lc = lane >> 4, x7 = lane & 7;
    const int e0 = blockIdx.x * M_CTA;

    // ---- edge_index dtype probe (int32 vs int64) ----
    if (t == 0) *(int*)(smem + FLAG_OFF) = 1;
    __syncthreads();
    const int* ei32 = (const int*)ei_raw;
    if (ei32[2 * t + 1] != 0) *(int*)(smem + FLAG_OFF) = 0;   // benign race
    __syncthreads();
    const int is64 = *(int*)(smem + FLAG_OFF);

    // ---- node indices (clamped): idx[0..95]=col, idx[96..191]=row ----
    if (t < 2 * M_CTA) {
        int m = (t < M_CTA) ? t : (t - M_CTA);
        int half = (t >= M_CTA);
        long long e = e0 + m; if (e >= E) e = E - 1;
        long long pos = (long long)half * E + e;
        int v = is64 ? (int)((const long long*)ei_raw)[pos] : ei32[pos];
        v = min(max(v, 0), n_nodes - 1);
        ((int*)(smem + IDX_OFF))[t] = v;
    }
    __syncthreads();

    // ---- H = relu(P[col] + Q[row]): warp-per-row gather, coalesced ----
    {
        const int* idx = (const int*)(smem + IDX_OFF);
#pragma unroll 2
        for (int e = 0; e < 8; ++e) {
            int m = warp * 8 + e;
            int colid = idx[m], rowid = idx[M_CTA + m];
            const uint4* pP = (const uint4*)(g_P + (size_t)colid * 512);
            const uint4* pQ = (const uint4*)(g_Q + (size_t)rowid * 512);
            uint4 p0 = __ldg(pP + lane),      q0 = __ldg(pQ + lane);
            uint4 p1 = __ldg(pP + 32 + lane), q1 = __ldg(pQ + 32 + lane);
            int xm = m & 7;
            *(uint4*)(smem + H_OFF + m * 1024 + ((lane ^ xm) * 16)) =
                h4fuse(p0, q0);
            *(uint4*)(smem + H_OFF + m * 1024 + (((lane + 32) ^ xm) * 16)) =
                h4fuse(p1, q1);
        }
    }
    __syncthreads();

    // ---- GEMM2: [96 x 512] @ W2[512 x 128], warp grid 3M x 4N (m32 x n32) ----
    const int wm = warp >> 2, wnn = warp & 3;
    const int rA = wm * 32 + (lane & 15);
    const uint32_t hB0 = sb + H_OFF + rA * 1024, hB1 = hB0 + 16 * 1024;

    float acc2[2][4][4];
#pragma unroll
    for (int a = 0; a < 2; ++a)
#pragma unroll
        for (int b = 0; b < 4; ++b)
#pragma unroll
            for (int d = 0; d < 4; ++d) acc2[a][b][d] = 0.f;
    {
        const uint4* bq2 = g_w2 + ((size_t)wnn * 2) * 32 + lane;
        uint4 q[2], qn[2];
        LOADB2(q, bq2);
#pragma unroll
        for (int ks = 0; ks < 32; ks += 2) {
            LOADB2(qn, bq2 + (ks + 1) * 256);
            kstep8(acc2, hB0, hB1, (uint32_t)(((ks * 2 + lc) ^ x7) << 4), q);
            if (ks + 2 < 32) LOADB2(q, bq2 + (ks + 2) * 256);
            kstep8(acc2, hB0, hB1, (uint32_t)((((ks + 1) * 2 + lc) ^ x7) << 4), qn);
        }
    }

    // ---- readout: relu(acc2 + b2) . W3, smem reduction ----
    float pr[4] = {0.f, 0.f, 0.f, 0.f};
#pragma unroll
    for (int tm = 0; tm < 2; ++tm) {
#pragma unroll
        for (int tn = 0; tn < 4; ++tn) {
            int n0 = wnn * 32 + tn * 8 + (lane & 3) * 2;
            float bb0 = __ldg(b2 + n0), bb1 = __ldg(b2 + n0 + 1);
            float w0 = __ldg(W3 + n0), w1 = __ldg(W3 + n0 + 1);
            pr[tm * 2]     += fmaxf(acc2[tm][tn][0] + bb0, 0.f) * w0;
            pr[tm * 2]     += fmaxf(acc2[tm][tn][1] + bb1, 0.f) * w1;
            pr[tm * 2 + 1] += fmaxf(acc2[tm][tn][2] + bb0, 0.f) * w0;
            pr[tm * 2 + 1] += fmaxf(acc2[tm][tn][3] + bb1, 0.f) * w1;
        }
    }
    __syncthreads();                       // H reads done; reuse as scratch
    float* sRed = (float*)(smem + H_OFF);  // [96][16]
#pragma unroll
    for (int tm = 0; tm < 2; ++tm)
#pragma unroll
        for (int h = 0; h < 2; ++h) {
            int row = wm * 32 + tm * 16 + (lane >> 2) + h * 8;
            sRed[row * 16 + wnn * 4 + (lane & 3)] = pr[tm * 2 + h];
        }
    __syncthreads();
    if (t < M_CTA) {
        float ssum = 0.f;
#pragma unroll
        for (int i = 0; i < 16; ++i) ssum += sRed[t * 16 + i];
        int e = e0 + t;
        if (e < E) out[e] = ssum + __ldg(b3);
    }
}

// --------------------------------------------------------------- launcher ---
extern "C" void kernel_launch(void* const* d_in, const int* in_sizes, int n_in,
                              void* d_out, int out_size) {
    const float* emb = (const float*)d_in[0];
    const void*  ei  = d_in[1];          // edge_index [2,E], int32 or int64 (probed)
    const float* W1 = (const float*)d_in[3];
    const float* b1 = (const float*)d_in[4];
    const float* W2 = (const float*)d_in[5];
    const float* b2 = (const float*)d_in[6];
    const float* W3 = (const float*)d_in[7];
    const float* b3 = (const float*)d_in[8];
    float* out = (float*)d_out;

    int E = in_sizes[1] / 2;
    int n_nodes = in_sizes[0] / HID;
    if (n_nodes > MAXN) n_nodes = MAXN;   // static-table capacity guard
    int blocks = (E + M_CTA - 1) / M_CTA;

    prep_pack<<<(256 * 512 + 512 * 128 + 255) / 256, 256>>>(W1, W2);
    prep_pq<<<(n_nodes + 31) / 32, 128>>>(emb, b1, n_nodes);
    cudaFuncSetAttribute(mlp_hmma_kernel,
                         cudaFuncAttributeMaxDynamicSharedMemorySize, SMEM_TOTAL);
    mlp_hmma_kernel<<<blocks, NTHREADS, SMEM_TOTAL>>>(ei, b2, W3, b3,
                                                      out, E, n_nodes);
}